// round 14
// baseline (speedup 1.0000x reference)
#include <cuda_runtime.h>
#include <cuda_fp16.h>
#include <cstdint>

#define BATCH 2
#define NSEQ  4096
#define CDIM  384
#define NH    6
#define HD    64
#define BH_TOT (BATCH * NH)
#define QK_SCALE 0.125f
#define L2E 1.4426950408889634f
#define NSPLIT 3
#define NKB (NSEQ / 64)

// ================= scratch (allocation-free: __device__ globals) =============
__device__ __half g_xh[BATCH * NSEQ * CDIM];  // x as fp16 hi/lo
__device__ __half g_xl[BATCH * NSEQ * CDIM];
__device__ __half g_wqh[CDIM * 3 * CDIM];     // w_qkv hi only
__device__ __half g_wph[CDIM * CDIM];         // w_proj hi only

__device__ __half g_qh[BH_TOT * NSEQ * HD];   // [BH,N,64] pre-scaled, hi only
__device__ __half g_kh[BH_TOT * NSEQ * HD];   // K hi only
__device__ __half g_vh[BH_TOT * NSEQ * HD];   // V hi only

__device__ float  g_opart[NSPLIT * BH_TOT * NSEQ * HD];  // split-KV partial O
__device__ float2 g_ml[NSPLIT * BH_TOT * NSEQ];          // per-row (m, l)

__device__ __half g_oh[BATCH * NSEQ * CDIM];  // attention out hi/lo
__device__ __half g_ol[BATCH * NSEQ * CDIM];

__device__ __forceinline__ float ex2f_fast(float x) {
    float y;
    asm("ex2.approx.f32 %0, %1;" : "=f"(y) : "f"(x));
    return y;
}

// packed fp16x2 exp2
__device__ __forceinline__ uint32_t ex2_h2(uint32_t t) {
    uint32_t y;
    asm("ex2.approx.f16x2 %0, %1;" : "=r"(y) : "r"(t));
    return y;
}

// fp16 split: hi pair + exact residual pair
__device__ __forceinline__ void split2(float a, float b, uint32_t& hi, uint32_t& lo) {
    __half2 h = __floats2half2_rn(a, b);
    hi = *reinterpret_cast<uint32_t*>(&h);
    float2 hf = __half22float2(h);
    __half2 l = __floats2half2_rn(a - hf.x, b - hf.y);
    lo = *reinterpret_cast<uint32_t*>(&l);
}

__device__ __forceinline__ uint32_t pack_h2(float a, float b) {
    __half2 h = __floats2half2_rn(a, b);
    return *reinterpret_cast<uint32_t*>(&h);
}

__device__ __forceinline__ float2 unpack_h2(uint32_t u) {
    __half2 h = *reinterpret_cast<__half2*>(&u);
    return __half22float2(h);
}

__device__ __forceinline__ uint32_t smem_u32(const void* p) {
    uint32_t a;
    asm("{ .reg .u64 t; cvta.to.shared.u64 t, %1; cvt.u32.u64 %0, t; }" : "=r"(a) : "l"(p));
    return a;
}

__device__ __forceinline__ void ldsm_x4(uint32_t* r, uint32_t addr) {
    asm volatile("ldmatrix.sync.aligned.m8n8.x4.shared.b16 {%0,%1,%2,%3}, [%4];"
                 : "=r"(r[0]), "=r"(r[1]), "=r"(r[2]), "=r"(r[3]) : "r"(addr));
}
__device__ __forceinline__ void ldsm_x4_t(uint32_t* r, uint32_t addr) {
    asm volatile("ldmatrix.sync.aligned.m8n8.x4.trans.shared.b16 {%0,%1,%2,%3}, [%4];"
                 : "=r"(r[0]), "=r"(r[1]), "=r"(r[2]), "=r"(r[3]) : "r"(addr));
}

#define MMA16816(d, a, b) \
    asm volatile( \
        "mma.sync.aligned.m16n8k16.row.col.f32.f16.f16.f32 " \
        "{%0,%1,%2,%3}, {%4,%5,%6,%7}, {%8,%9}, {%0,%1,%2,%3};" \
        : "+f"((d)[0]), "+f"((d)[1]), "+f"((d)[2]), "+f"((d)[3]) \
        : "r"((a)[0]), "r"((a)[1]), "r"((a)[2]), "r"((a)[3]), \
          "r"((b)[0]), "r"((b)[1]))

#define CP16(dst_u32, src_ptr) \
    asm volatile("cp.async.cg.shared.global [%0], [%1], 16;" :: "r"(dst_u32), "l"(src_ptr))
#define CP_COMMIT() asm volatile("cp.async.commit_group;" ::: "memory")
#define CP_WAIT1()  asm volatile("cp.async.wait_group 1;" ::: "memory")
#define CP_WAIT0()  asm volatile("cp.async.wait_group 0;" ::: "memory")

// ============================================================
// Kernel 0: fp32 -> fp16 conversion. x: hi+lo; wq/wp: hi only.
// ============================================================
#define NX4  (BATCH * NSEQ * CDIM / 4)
#define NWQ4 (CDIM * 3 * CDIM / 4)
#define NWP4 (CDIM * CDIM / 4)
#define NCONV_BLOCKS ((NX4 + NWQ4 + NWP4 + 255) / 256)

__global__ __launch_bounds__(256) void convert_kernel(
    const float* __restrict__ x, const float* __restrict__ wq,
    const float* __restrict__ wp)
{
    int i = blockIdx.x * 256 + threadIdx.x;
    if (i < NX4) {
        float4 f = *(const float4*)(x + (size_t)i * 4);
        uint2 h, l;
        split2(f.x, f.y, h.x, l.x);
        split2(f.z, f.w, h.y, l.y);
        *(uint2*)(g_xh + (size_t)i * 4) = h;
        *(uint2*)(g_xl + (size_t)i * 4) = l;
    } else if (i < NX4 + NWQ4) {
        int off = i - NX4;
        float4 f = *(const float4*)(wq + (size_t)off * 4);
        uint2 h;
        h.x = pack_h2(f.x, f.y);
        h.y = pack_h2(f.z, f.w);
        *(uint2*)(g_wqh + (size_t)off * 4) = h;
    } else if (i < NX4 + NWQ4 + NWP4) {
        int off = i - NX4 - NWQ4;
        float4 f = *(const float4*)(wp + (size_t)off * 4);
        uint2 h;
        h.x = pack_h2(f.x, f.y);
        h.y = pack_h2(f.z, f.w);
        *(uint2*)(g_wph + (size_t)off * 4) = h;
    }
}

// ============================================================
// Shared GEMM compute: 128x128 CTA, 8 warps (4m x 2n), K-step 32,
// 2-chain (A hi/lo x B hi), cp.async double-buffered, ldsm.x4.
// ============================================================
#define GAH 0
#define GAL 10240
#define GBH 20480
#define GBUF 28672
#define GEMM_SMEM (2 * GBUF)

__device__ __forceinline__ void gemm_compute_step(
    float acc[2][8][4], uint32_t bb, int wm, int wn, int lane)
{
    const int l8 = lane & 7, l16 = lane & 15;
    const int jsel = lane >> 4;
#pragma unroll
    for (int s = 0; s < 2; s++) {
        uint32_t ah[2][4], al[2][4];
        uint32_t arow = (uint32_t)((wm + l8 + 8 * ((lane >> 3) & 1)) * 80 +
                                   (2 * s + (lane >> 4)) * 16);
        ldsm_x4(ah[0], bb + GAH + arow);
        ldsm_x4(ah[1], bb + GAH + arow + 16 * 80);
        ldsm_x4(al[0], bb + GAL + arow);
        ldsm_x4(al[1], bb + GAL + arow + 16 * 80);

        uint32_t bf[8][2];
        const uint32_t brow = (uint32_t)((s * 16 + l16) * 256);
#pragma unroll
        for (int j = 0; j < 8; j += 2) {
            int jj = (wn >> 3) + j + jsel;
            uint32_t r[4];
            ldsm_x4_t(r, bb + GBH + brow + (uint32_t)(((jj ^ l8) << 4)));
            bf[j][0] = r[0]; bf[j][1] = r[1];
            bf[j + 1][0] = r[2]; bf[j + 1][1] = r[3];
        }
#pragma unroll
        for (int j = 0; j < 8; j++) {
            MMA16816(acc[0][j], ah[0], bf[j]);
            MMA16816(acc[1][j], ah[1], bf[j]);
        }
#pragma unroll
        for (int j = 0; j < 8; j++) {
            MMA16816(acc[0][j], al[0], bf[j]);
            MMA16816(acc[1][j], al[1], bf[j]);
        }
    }
}

// ============================================================
// Kernel 1: QKV GEMM -> Q(x0.125)/K/V hi [BH,N,64]
// ============================================================
__global__ __launch_bounds__(256, 2) void qkv_tc_kernel()
{
    extern __shared__ char sm[];
    const uint32_t sb = smem_u32(sm);
    const int tid = threadIdx.x, warp = tid >> 5, lane = tid & 31;
    const int wm = (warp & 3) * 32, wn = (warp >> 2) * 64;
    const int row0 = blockIdx.y * 128, col0 = blockIdx.x * 128;

    float acc[2][8][4];
#pragma unroll
    for (int mi = 0; mi < 2; mi++)
#pragma unroll
        for (int j = 0; j < 8; j++)
#pragma unroll
            for (int i = 0; i < 4; i++) acc[mi][j][i] = 0.0f;

    auto stage = [&](int buf, int k0) {
        uint32_t base = sb + buf * GBUF;
#pragma unroll
        for (int it = 0; it < 2; it++) {
            int idx = tid + it * 256;
            int row = idx >> 2, ch = idx & 3;
            size_t g = (size_t)(row0 + row) * CDIM + k0 + ch * 8;
            CP16(base + GAH + row * 80 + ch * 16, g_xh + g);
            CP16(base + GAL + row * 80 + ch * 16, g_xl + g);
        }
#pragma unroll
        for (int it = 0; it < 2; it++) {
            int idx = tid + it * 256;
            int row = idx >> 4, ch = idx & 15;
            size_t g = (size_t)(k0 + row) * (3 * CDIM) + col0 + ch * 8;
            uint32_t sw = (uint32_t)(row * 256 + ((ch ^ (row & 7)) << 4));
            CP16(base + GBH + sw, g_wqh + g);
        }
    };

    stage(0, 0);
    CP_COMMIT();

    const int NIT = CDIM / 32;
    for (int kt = 0; kt < NIT; kt++) {
        if (kt < NIT - 1) {
            stage((kt + 1) & 1, (kt + 1) * 32);
            CP_COMMIT();
            CP_WAIT1();
        } else {
            CP_WAIT0();
        }
        __syncthreads();
        gemm_compute_step(acc, sb + (uint32_t)((kt & 1) * GBUF), wm, wn, lane);
        __syncthreads();
    }

    // epilogue: hi only
    const int gid = lane >> 2, tq = lane & 3;
#pragma unroll
    for (int j = 0; j < 8; j++) {
        int col = col0 + wn + j * 8 + tq * 2;
        int which = col / CDIM, cm = col % CDIM;
        int h = cm / HD, d = cm % HD;
        float sc = (which == 0) ? QK_SCALE : 1.0f;
        __half* hp = (which == 0) ? g_qh : (which == 1) ? g_kh : g_vh;
#pragma unroll
        for (int mi = 0; mi < 2; mi++) {
#pragma unroll
            for (int rg = 0; rg < 2; rg++) {
                int m = row0 + wm + mi * 16 + gid + rg * 8;
                int b = m >> 12, n = m & (NSEQ - 1);
                size_t base = (((size_t)(b * NH + h)) * NSEQ + n) * HD + d;
                *(uint32_t*)&hp[base] =
                    pack_h2(acc[mi][j][rg * 2] * sc, acc[mi][j][rg * 2 + 1] * sc);
            }
        }
    }
}

// ============================================================
// Kernel 2: flash attention, single-chain fp16, 3-way split-KV,
// ldsm.x4 loads, fp16x2 softmax exp, ballot-guarded rescale.
// ============================================================
#define STG 16384
#define SKH 0
#define SVH 8192
#define ATT_SMEM (2 * STG)

__global__ __launch_bounds__(256, 2) void attn_mma_kernel()
{
    extern __shared__ char smem[];
    const uint32_t sbase = smem_u32(smem);

    const int tid = threadIdx.x;
    const int warp = tid >> 5, lane = tid & 31;
    const int bh = blockIdx.y;
    const int z = blockIdx.z;
    const int r0 = blockIdx.x * 128;
    const int R = r0 + warp * 16;

    const int l8 = lane & 7;
    const int hseg = (lane >> 3) & 1;
    const int jsel = lane >> 4;
    const int rA = R + (lane >> 2);
    const int kcol = (lane & 3) * 2;

    const int kb0 = (z * NKB) / NSPLIT;
    const int kb1 = ((z + 1) * NKB) / NSPLIT;
    const int nb = kb1 - kb0;

    const __half* Qh = g_qh + (size_t)bh * NSEQ * HD;
    const __half* Kh = g_kh + (size_t)bh * NSEQ * HD;
    const __half* Vh = g_vh + (size_t)bh * NSEQ * HD;

    // Q hi a-fragments in registers
    uint32_t qah[4][4];
#pragma unroll
    for (int s = 0; s < 4; s++) {
        qah[s][0] = *(const uint32_t*)&Qh[(size_t)rA * HD + s * 16 + kcol];
        qah[s][1] = *(const uint32_t*)&Qh[(size_t)(rA + 8) * HD + s * 16 + kcol];
        qah[s][2] = *(const uint32_t*)&Qh[(size_t)rA * HD + s * 16 + 8 + kcol];
        qah[s][3] = *(const uint32_t*)&Qh[(size_t)(rA + 8) * HD + s * 16 + 8 + kcol];
    }

    float of[8][4];
#pragma unroll
    for (int j = 0; j < 8; j++)
#pragma unroll
        for (int i = 0; i < 4; i++) of[j][i] = 0.0f;
    float mA = -1e30f, mB = -1e30f, lA = 0.0f, lB = 0.0f;

    const uint32_t krow = (uint32_t)(l8 * 128);

    auto stage = [&](int st, int kr0) {
#pragma unroll
        for (int it = 0; it < 2; it++) {
            int idx = tid + it * 256;
            int row = idx >> 3, ch = idx & 7;
            uint32_t sw = (uint32_t)(st * STG + row * 128 + ((ch ^ (row & 7)) << 4));
            size_t g = (size_t)(kr0 + row) * HD + ch * 8;
            CP16(sbase + sw + SKH, Kh + g);
            CP16(sbase + sw + SVH, Vh + g);
        }
    };

    stage(0, kb0 * 64);
    CP_COMMIT();

    for (int it = 0; it < nb; it++) {
        if (it < nb - 1) {
            stage((it + 1) & 1, (kb0 + it + 1) * 64);
            CP_COMMIT();
            CP_WAIT1();
        } else {
            CP_WAIT0();
        }
        __syncthreads();
        const uint32_t stb = sbase + (uint32_t)((it & 1) * STG);

        // ---- S = Q K^T (single chain, ldsm.x4) ----
        float sf[8][4];
#pragma unroll
        for (int j = 0; j < 8; j++)
#pragma unroll
            for (int i = 0; i < 4; i++) sf[j][i] = 0.0f;

#pragma unroll
        for (int s = 0; s < 4; s++) {
            uint32_t chsw = (uint32_t)((((2 * s + hseg) ^ l8) << 4));
#pragma unroll
            for (int jc = 0; jc < 8; jc += 4) {
                uint32_t kbf[4][2];
#pragma unroll
                for (int jj = 0; jj < 4; jj += 2) {
                    uint32_t r[4];
                    ldsm_x4(r, stb + SKH + (uint32_t)((jc + jj + jsel) * 1024) + krow + chsw);
                    kbf[jj][0] = r[0]; kbf[jj][1] = r[1];
                    kbf[jj + 1][0] = r[2]; kbf[jj + 1][1] = r[3];
                }
#pragma unroll
                for (int j = 0; j < 4; j++) MMA16816(sf[jc + j], qah[s], kbf[j]);
            }
        }

        // ---- online softmax (fp16x2 exp) ----
        float mxA = sf[0][0], mxB = sf[0][2];
#pragma unroll
        for (int j = 0; j < 8; j++) {
            mxA = fmaxf(mxA, fmaxf(sf[j][0], sf[j][1]));
            mxB = fmaxf(mxB, fmaxf(sf[j][2], sf[j][3]));
        }
        mxA = fmaxf(mxA, __shfl_xor_sync(0xffffffffu, mxA, 1));
        mxA = fmaxf(mxA, __shfl_xor_sync(0xffffffffu, mxA, 2));
        mxB = fmaxf(mxB, __shfl_xor_sync(0xffffffffu, mxB, 1));
        mxB = fmaxf(mxB, __shfl_xor_sync(0xffffffffu, mxB, 2));

        float mnA = fmaxf(mA, mxA), mnB = fmaxf(mB, mxB);
        float corrA = ex2f_fast((mA - mnA) * L2E);
        float corrB = ex2f_fast((mB - mnB) * L2E);
        mA = mnA; mB = mnB;
        const float nlA = mnA * L2E, nlB = mnB * L2E;

        // P in packed fp16 directly (also the PV MMA operand)
        uint32_t pA[8], pB[8];
        float sumA = 0.0f, sumB = 0.0f;
#pragma unroll
        for (int j = 0; j < 8; j++) {
            float t0 = fmaf(sf[j][0], L2E, -nlA);
            float t1 = fmaf(sf[j][1], L2E, -nlA);
            float t2 = fmaf(sf[j][2], L2E, -nlB);
            float t3 = fmaf(sf[j][3], L2E, -nlB);
            pA[j] = ex2_h2(pack_h2(t0, t1));
            pB[j] = ex2_h2(pack_h2(t2, t3));
            float2 fa = unpack_h2(pA[j]);
            float2 fb = unpack_h2(pB[j]);
            sumA += fa.x + fa.y;
            sumB += fb.x + fb.y;
        }
        lA = lA * corrA + sumA;
        lB = lB * corrB + sumB;

        // rescale O only if any lane's max moved (warp-uniform branch)
        if (__ballot_sync(0xffffffffu, (corrA != 1.0f) || (corrB != 1.0f))) {
#pragma unroll
            for (int j = 0; j < 8; j++) {
                of[j][0] *= corrA; of[j][1] *= corrA;
                of[j][2] *= corrB; of[j][3] *= corrB;
            }
        }

        // ---- O += P V (single chain, ldsm.x4.trans) ----
#pragma unroll
        for (int s = 0; s < 4; s++) {
            uint32_t pah[4];
            pah[0] = pA[2 * s];
            pah[1] = pB[2 * s];
            pah[2] = pA[2 * s + 1];
            pah[3] = pB[2 * s + 1];

            uint32_t vrow = (uint32_t)((16 * s + 8 * hseg + l8) * 128);
#pragma unroll
            for (int jc = 0; jc < 8; jc += 4) {
                uint32_t vbf[4][2];
#pragma unroll
                for (int jj = 0; jj < 4; jj += 2) {
                    uint32_t r[4];
                    ldsm_x4_t(r, stb + SVH + vrow +
                              (uint32_t)((((jc + jj + jsel) ^ l8) << 4)));
                    vbf[jj][0] = r[0]; vbf[jj][1] = r[1];
                    vbf[jj + 1][0] = r[2]; vbf[jj + 1][1] = r[3];
                }
#pragma unroll
                for (int j = 0; j < 4; j++) MMA16816(of[jc + j], pah, vbf[j]);
            }
        }
        __syncthreads();
    }

    // ---- epilogue: write PARTIAL O (un-normalized) + (m, l) ----
    lA += __shfl_xor_sync(0xffffffffu, lA, 1);
    lA += __shfl_xor_sync(0xffffffffu, lA, 2);
    lB += __shfl_xor_sync(0xffffffffu, lB, 1);
    lB += __shfl_xor_sync(0xffffffffu, lB, 2);

    float* opart = g_opart + (size_t)z * BH_TOT * NSEQ * HD + (size_t)bh * NSEQ * HD;
#pragma unroll
    for (int j = 0; j < 8; j++) {
        int c = j * 8 + kcol;
        float2 oa = make_float2(of[j][0], of[j][1]);
        float2 ob = make_float2(of[j][2], of[j][3]);
        *(float2*)&opart[(size_t)rA * HD + c] = oa;
        *(float2*)&opart[(size_t)(rA + 8) * HD + c] = ob;
    }
    if ((lane & 3) == 0) {
        size_t mlbase = (size_t)z * BH_TOT * NSEQ + (size_t)bh * NSEQ;
        g_ml[mlbase + rA] = make_float2(mA, lA);
        g_ml[mlbase + rA + 8] = make_float2(mB, lB);
    }
}

// ============================================================
// Kernel 2b: combine split-KV partials -> g_oh/g_ol [B,N,C]
// ============================================================
#define NCOMB_BLOCKS (BH_TOT * NSEQ * 16 / 256)

__global__ __launch_bounds__(256) void combine_kernel()
{
    int idx = blockIdx.x * 256 + threadIdx.x;
    int row = idx >> 4;                 // bh*NSEQ + n
    int dq = (idx & 15) * 4;

    float2 ml0 = g_ml[row];
    float2 ml1 = g_ml[BH_TOT * NSEQ + row];
    float2 ml2 = g_ml[2 * BH_TOT * NSEQ + row];
    float ms = fmaxf(ml0.x, fmaxf(ml1.x, ml2.x));
    float w0 = ex2f_fast((ml0.x - ms) * L2E);
    float w1 = ex2f_fast((ml1.x - ms) * L2E);
    float w2 = ex2f_fast((ml2.x - ms) * L2E);
    float inv = 1.0f / (ml0.y * w0 + ml1.y * w1 + ml2.y * w2);

    size_t pbase = (size_t)row * HD + dq;
    float4 o0 = *(const float4*)&g_opart[pbase];
    float4 o1 = *(const float4*)&g_opart[(size_t)BH_TOT * NSEQ * HD + pbase];
    float4 o2 = *(const float4*)&g_opart[2 * (size_t)BH_TOT * NSEQ * HD + pbase];

    float4 o;
    o.x = (o0.x * w0 + o1.x * w1 + o2.x * w2) * inv;
    o.y = (o0.y * w0 + o1.y * w1 + o2.y * w2) * inv;
    o.z = (o0.z * w0 + o1.z * w1 + o2.z * w2) * inv;
    o.w = (o0.w * w0 + o1.w * w1 + o2.w * w2) * inv;

    int bh = row >> 12;                 // row / NSEQ
    int n = row & (NSEQ - 1);
    int b = bh / NH, h = bh % NH;
    size_t obase = ((size_t)b * NSEQ + n) * CDIM + h * HD + dq;

    uint32_t h0, l0, h1, l1;
    split2(o.x, o.y, h0, l0);
    split2(o.z, o.w, h1, l1);
    uint2 uh; uh.x = h0; uh.y = h1;
    uint2 ul; ul.x = l0; ul.y = l1;
    *(uint2*)&g_oh[obase] = uh;
    *(uint2*)&g_ol[obase] = ul;
}

// ============================================================
// Kernel 3: proj GEMM (2-chain) + bias -> out fp32
// ============================================================
__global__ __launch_bounds__(256, 2) void proj_tc_kernel(
    const float* __restrict__ bias, float* __restrict__ out)
{
    extern __shared__ char sm[];
    const uint32_t sb = smem_u32(sm);
    const int tid = threadIdx.x, warp = tid >> 5, lane = tid & 31;
    const int wm = (warp & 3) * 32, wn = (warp >> 2) * 64;
    const int row0 = blockIdx.y * 128, col0 = blockIdx.x * 128;

    float acc[2][8][4];
#pragma unroll
    for (int mi = 0; mi < 2; mi++)
#pragma unroll
        for (int j = 0; j < 8; j++)
#pragma unroll
            for (int i = 0; i < 4; i++) acc[mi][j][i] = 0.0f;

    auto stage = [&](int buf, int k0) {
        uint32_t base = sb + buf * GBUF;
#pragma unroll
        for (int it = 0; it < 2; it++) {
            int idx = tid + it * 256;
            int row = idx >> 2, ch = idx & 3;
            size_t g = (size_t)(row0 + row) * CDIM + k0 + ch * 8;
            CP16(base + GAH + row * 80 + ch * 16, g_oh + g);
            CP16(base + GAL + row * 80 + ch * 16, g_ol + g);
        }
#pragma unroll
        for (int it = 0; it < 2; it++) {
            int idx = tid + it * 256;
            int row = idx >> 4, ch = idx & 15;
            size_t g = (size_t)(k0 + row) * CDIM + col0 + ch * 8;
            uint32_t sw = (uint32_t)(row * 256 + ((ch ^ (row & 7)) << 4));
            CP16(base + GBH + sw, g_wph + g);
        }
    };

    stage(0, 0);
    CP_COMMIT();

    const int NIT = CDIM / 32;
    for (int kt = 0; kt < NIT; kt++) {
        if (kt < NIT - 1) {
            stage((kt + 1) & 1, (kt + 1) * 32);
            CP_COMMIT();
            CP_WAIT1();
        } else {
            CP_WAIT0();
        }
        __syncthreads();
        gemm_compute_step(acc, sb + (uint32_t)((kt & 1) * GBUF), wm, wn, lane);
        __syncthreads();
    }

    const int gid = lane >> 2, tq = lane & 3;
#pragma unroll
    for (int j = 0; j < 8; j++) {
        int col = col0 + wn + j * 8 + tq * 2;
        float2 bv = *(const float2*)&bias[col];
#pragma unroll
        for (int mi = 0; mi < 2; mi++) {
#pragma unroll
            for (int rg = 0; rg < 2; rg++) {
                int m = row0 + wm + mi * 16 + gid + rg * 8;
                float2 o = make_float2(acc[mi][j][rg * 2] + bv.x,
                                       acc[mi][j][rg * 2 + 1] + bv.y);
                *(float2*)&out[(size_t)m * CDIM + col] = o;
            }
        }
    }
}

// ============================================================
extern "C" void kernel_launch(void* const* d_in, const int* in_sizes, int n_in,
                              void* d_out, int out_size)
{
    const float* x      = (const float*)d_in[0];
    const float* w_qkv  = (const float*)d_in[1];
    const float* w_proj = (const float*)d_in[2];
    const float* b_proj = (const float*)d_in[3];
    float* out = (float*)d_out;

    (void)in_sizes; (void)n_in; (void)out_size;

    cudaFuncSetAttribute(qkv_tc_kernel,
                         cudaFuncAttributeMaxDynamicSharedMemorySize, GEMM_SMEM);
    cudaFuncSetAttribute(attn_mma_kernel,
                         cudaFuncAttributeMaxDynamicSharedMemorySize, ATT_SMEM);
    cudaFuncSetAttribute(proj_tc_kernel,
                         cudaFuncAttributeMaxDynamicSharedMemorySize, GEMM_SMEM);

    convert_kernel<<<NCONV_BLOCKS, 256>>>(x, w_qkv, w_proj);

    qkv_tc_kernel<<<dim3(3 * CDIM / 128, (BATCH * NSEQ) / 128), 256, GEMM_SMEM>>>();

    attn_mma_kernel<<<dim3(NSEQ / 128, BH_TOT, NSPLIT), 256, ATT_SMEM>>>();

    combine_kernel<<<NCOMB_BLOCKS, 256>>>();

    proj_tc_kernel<<<dim3(CDIM / 128, (BATCH * NSEQ) / 128), 256, GEMM_SMEM>>>(b_proj, out);
}